// round 1
// baseline (speedup 1.0000x reference)
#include <cuda_runtime.h>

// StrictOrthogonal: Q = orth(X) for X in C^{16384 x 32}, via CholeskyQR + one
// linearized Jacobi refinement sweep (sweeps 2-3 are provably < 1e-6 rel noise).
//
// Pipeline:
//   A) gram_kernel : per-CTA partial G0 = X^H X   (128 CTAs, warp-shuffle outer product)
//   B) solve_kernel: reduce partials -> G0; chol(G0)=L L^H; W = L^{-1};
//                    G = W G0 W^H (= Q^H Q); T = I - 0.5 off(G);
//                    S = W^H T diag(rsqrt(diag(G)+1e-10))   (1 CTA, 1024 thr)
//   C) apply_kernel: out = X * S                   (128 CTAs, warp-shuffle row GEMM)

#define M_ROWS 16384
#define R 32
#define NCTA_A 128
#define ROWS_PER_CTA (M_ROWS / NCTA_A)          // 128
#define WARPS_A 8
#define ROWS_PER_WARP (ROWS_PER_CTA / WARPS_A)  // 16

__device__ float2 d_partial[NCTA_A][R * R];
__device__ float2 d_S[R * R];

// ---------------------------------------------------------------------------
// Kernel A: partial Gram matrices. Lane l accumulates G0 row l:
//   G0[l][j] += conj(x_{m,l}) * x_{m,j}
// ---------------------------------------------------------------------------
__global__ __launch_bounds__(256) void gram_kernel(const float2* __restrict__ x) {
    const int lane = threadIdx.x & 31;
    const int warp = threadIdx.x >> 5;
    const int row0 = blockIdx.x * ROWS_PER_CTA + warp * ROWS_PER_WARP;

    float accr[R], acci[R];
#pragma unroll
    for (int j = 0; j < R; j++) { accr[j] = 0.f; acci[j] = 0.f; }

    const float2* p = x + (size_t)row0 * R + lane;
#pragma unroll 4
    for (int m = 0; m < ROWS_PER_WARP; m++) {
        float2 v = p[m * R];
#pragma unroll
        for (int j = 0; j < R; j++) {
            float br = __shfl_sync(0xffffffffu, v.x, j);
            float bi = __shfl_sync(0xffffffffu, v.y, j);
            // conj(a)*b : (ax*bx + ay*by) + i(ax*by - ay*bx)
            accr[j] += v.x * br + v.y * bi;
            acci[j] += v.x * bi - v.y * br;
        }
    }

    // cross-warp reduce: 8 warps -> 4 slabs -> 1
    __shared__ float2 sAcc[4][R][R + 1];  // +1 pad: avoid 256B-stride STS conflicts
    if (warp < 4) {
#pragma unroll
        for (int j = 0; j < R; j++) sAcc[warp][lane][j] = make_float2(accr[j], acci[j]);
    }
    __syncthreads();
    if (warp >= 4) {
#pragma unroll
        for (int j = 0; j < R; j++) {
            float2 t = sAcc[warp - 4][lane][j];
            sAcc[warp - 4][lane][j] = make_float2(t.x + accr[j], t.y + acci[j]);
        }
    }
    __syncthreads();
    for (int e = threadIdx.x; e < R * R; e += 256) {
        int i = e >> 5, j = e & 31;
        float2 a = sAcc[0][i][j], b = sAcc[1][i][j];
        float2 c = sAcc[2][i][j], d = sAcc[3][i][j];
        d_partial[blockIdx.x][e] =
            make_float2((a.x + b.x) + (c.x + d.x), (a.y + b.y) + (c.y + d.y));
    }
}

// ---------------------------------------------------------------------------
// Kernel B: single-CTA 32x32 solve. Thread (i,j) = (warp, lane) owns entry (i,j).
// ---------------------------------------------------------------------------
__global__ __launch_bounds__(1024) void solve_kernel() {
    const int tid = threadIdx.x;
    const int i = tid >> 5;   // warp = matrix row
    const int j = tid & 31;   // lane = matrix col

    __shared__ float2 sG0[R][R + 1];
    __shared__ float2 sL[R][R + 1];
    __shared__ float2 sW[R][R + 1];
    __shared__ float2 sP[R][R + 1];
    __shared__ float2 sT[R][R + 1];
    __shared__ float  sScale[R];

    // 1) reduce 128 partials -> G0
    {
        float2 g = make_float2(0.f, 0.f);
#pragma unroll 8
        for (int c = 0; c < NCTA_A; c++) {
            float2 t = d_partial[c][tid];
            g.x += t.x; g.y += t.y;
        }
        sG0[i][j] = g;
        sL[i][j]  = g;
    }
    __syncthreads();

    // 2) Cholesky (lower) in-place on sL: G0 = L L^H
    for (int k = 0; k < R; k++) {
        float inv = rsqrtf(sL[k][k].x);
        __syncthreads();
        if (j == k && i >= k) { sL[i][k].x *= inv; sL[i][k].y *= inv; }
        __syncthreads();
        if (i > k && j > k && j <= i) {
            float2 a = sL[i][k], b = sL[j][k];
            // sL[i][j] -= a * conj(b)
            sL[i][j].x -= a.x * b.x + a.y * b.y;
            sL[i][j].y -= a.y * b.x - a.x * b.y;
        }
        __syncthreads();
    }

    // 3) W = L^{-1} (lower): warp c computes column c by forward substitution;
    //    lane j holds w[j].
    {
        const int c = i;
        float wr = 0.f, wi = 0.f;
        if (j == c) wr = 1.0f / sL[c][c].x;
        for (int r = c + 1; r < R; r++) {
            float2 Lr = sL[r][j];
            float pr = 0.f, pi = 0.f;
            if (j >= c && j < r) {
                // L[r][j] * w[j]
                pr = Lr.x * wr - Lr.y * wi;
                pi = Lr.x * wi + Lr.y * wr;
            }
#pragma unroll
            for (int o = 16; o > 0; o >>= 1) {
                pr += __shfl_xor_sync(0xffffffffu, pr, o);
                pi += __shfl_xor_sync(0xffffffffu, pi, o);
            }
            float rinv = 1.0f / sL[r][r].x;
            if (j == r) { wr = -pr * rinv; wi = -pi * rinv; }
        }
        sW[j][c] = make_float2(wr, wi);  // zeros above diagonal by construction
    }
    __syncthreads();

    // 4) P = G0 * W^H : P[i][j] = sum_k G0[i][k] * conj(W[j][k])
    {
        float pr = 0.f, pi = 0.f;
#pragma unroll
        for (int k = 0; k < R; k++) {
            float2 a = sG0[i][k];
            float2 b = sW[j][k];
            pr += a.x * b.x + a.y * b.y;
            pi += a.y * b.x - a.x * b.y;
        }
        sP[i][j] = make_float2(pr, pi);
    }
    __syncthreads();

    // 5) G = W * P  (= Q^H Q); build T = I - 0.5 off(G), scale_j = rsqrt(G_jj + 1e-10)
    {
        float gr = 0.f, gi = 0.f;
#pragma unroll
        for (int k = 0; k < R; k++) {
            float2 a = sW[i][k];
            float2 b = sP[k][j];
            gr += a.x * b.x - a.y * b.y;
            gi += a.x * b.y + a.y * b.x;
        }
        if (i == j) {
            sScale[j] = rsqrtf(gr + 1e-10f);
            sT[i][j] = make_float2(1.f, 0.f);
        } else {
            sT[i][j] = make_float2(-0.5f * gr, -0.5f * gi);
        }
    }
    __syncthreads();

    // 6) S = W^H * T * diag(scale): S[i][j] = scale_j * sum_k conj(W[k][i]) * T[k][j]
    {
        float sr = 0.f, si = 0.f;
#pragma unroll
        for (int k = 0; k < R; k++) {
            float2 a = sW[k][i];
            float2 b = sT[k][j];
            sr += a.x * b.x + a.y * b.y;
            si += a.x * b.y - a.y * b.x;
        }
        float sc = sScale[j];
        d_S[i * R + j] = make_float2(sr * sc, si * sc);
    }
}

// ---------------------------------------------------------------------------
// Kernel C: out = X * S. Warp per row; lane j computes y_j = sum_k x_k * S[k][j].
// ---------------------------------------------------------------------------
__global__ __launch_bounds__(256) void apply_kernel(const float2* __restrict__ x,
                                                    float2* __restrict__ out) {
    const int lane = threadIdx.x & 31;
    const int warp = threadIdx.x >> 5;
    const int row0 = blockIdx.x * ROWS_PER_CTA + warp * ROWS_PER_WARP;

    float2 s[R];
#pragma unroll
    for (int k = 0; k < R; k++) s[k] = d_S[k * R + lane];

    const float2* p = x + (size_t)row0 * R + lane;
    float2* q = out + (size_t)row0 * R + lane;
#pragma unroll 2
    for (int m = 0; m < ROWS_PER_WARP; m++) {
        float2 v = p[m * R];
        float yr = 0.f, yi = 0.f;
#pragma unroll
        for (int k = 0; k < R; k++) {
            float xr = __shfl_sync(0xffffffffu, v.x, k);
            float xi = __shfl_sync(0xffffffffu, v.y, k);
            // x_k * S[k][j]
            yr += xr * s[k].x - xi * s[k].y;
            yi += xr * s[k].y + xi * s[k].x;
        }
        q[m * R] = make_float2(yr, yi);
    }
}

extern "C" void kernel_launch(void* const* d_in, const int* in_sizes, int n_in,
                              void* d_out, int out_size) {
    const float2* x = (const float2*)d_in[0];
    float2* out = (float2*)d_out;
    gram_kernel<<<NCTA_A, 256>>>(x);
    solve_kernel<<<1, 1024>>>();
    apply_kernel<<<NCTA_A, 256>>>(x, out);
}

// round 5
// speedup vs baseline: 1.2441x; 1.2441x over previous
#include <cuda_runtime.h>

// StrictOrthogonal: Q = orth(X), X in C^{16384 x 32}, via CholeskyQR + one
// linearized Jacobi refinement sweep (sweeps 2-3 are < 1e-6 rel noise).
//
//   A) gram_kernel : 512 CTAs x 256 thr, per-CTA partial G0 = X^H X
//   B) solve_kernel: 16 CTAs x 1024 thr; each reduces a 32-partial chunk;
//                    last CTA (atomic ticket) reduces 16 chunks and runs the
//                    32x32 solve: chol, W=L^{-1}, G=W G0 W^H, T=I-0.5 off(G),
//                    S = W^H T diag(rsqrt(diag G))
//   C) apply_kernel: 512 CTAs x 256 thr, out = X * S

#define M_ROWS 16384
#define R 32
#define NCTA_A 512
#define WARPS_A 8
#define ROWS_PER_WARP (M_ROWS / (NCTA_A * WARPS_A))   // 4
#define NCTA_B 16
#define CHUNK (NCTA_A / NCTA_B)                        // 32

__device__ float2 d_partial[NCTA_A][R * R];
__device__ float2 d_chunk[NCTA_B][R * R];
__device__ int    d_ticket;
__device__ float2 d_S[R * R];

// ---------------------------------------------------------------------------
// Kernel A: partial Gram. Lane l accumulates G0 row l over this warp's rows.
// ---------------------------------------------------------------------------
__global__ __launch_bounds__(256) void gram_kernel(const float2* __restrict__ x) {
    const int lane = threadIdx.x & 31;
    const int warp = threadIdx.x >> 5;
    const int row0 = (blockIdx.x * WARPS_A + warp) * ROWS_PER_WARP;

    float accr[R], acci[R];
#pragma unroll
    for (int j = 0; j < R; j++) { accr[j] = 0.f; acci[j] = 0.f; }

    const float2* p = x + (size_t)row0 * R + lane;
    float2 v[ROWS_PER_WARP];
#pragma unroll
    for (int m = 0; m < ROWS_PER_WARP; m++) v[m] = p[m * R];

#pragma unroll
    for (int m = 0; m < ROWS_PER_WARP; m++) {
#pragma unroll
        for (int j = 0; j < R; j++) {
            float br = __shfl_sync(0xffffffffu, v[m].x, j);
            float bi = __shfl_sync(0xffffffffu, v[m].y, j);
            // conj(a)*b : (ax*bx + ay*by) + i(ax*by - ay*bx)
            accr[j] += v[m].x * br + v[m].y * bi;
            acci[j] += v[m].x * bi - v[m].y * br;
        }
    }

    // cross-warp reduce: 8 warps -> 4 slabs -> 1
    __shared__ float2 sAcc[4][R][R + 1];
    if (warp < 4) {
#pragma unroll
        for (int j = 0; j < R; j++) sAcc[warp][lane][j] = make_float2(accr[j], acci[j]);
    }
    __syncthreads();
    if (warp >= 4) {
#pragma unroll
        for (int j = 0; j < R; j++) {
            float2 t = sAcc[warp - 4][lane][j];
            sAcc[warp - 4][lane][j] = make_float2(t.x + accr[j], t.y + acci[j]);
        }
    }
    __syncthreads();
    for (int e = threadIdx.x; e < R * R; e += 256) {
        int i = e >> 5, j = e & 31;
        float2 a = sAcc[0][i][j], b = sAcc[1][i][j];
        float2 c = sAcc[2][i][j], d = sAcc[3][i][j];
        d_partial[blockIdx.x][e] =
            make_float2((a.x + b.x) + (c.x + d.x), (a.y + b.y) + (c.y + d.y));
    }
}

// ---------------------------------------------------------------------------
// Kernel B: 16 CTAs reduce chunks; last CTA does the 32x32 solve.
// Thread (i,j) = (warp, lane) owns matrix entry (i,j).
// ---------------------------------------------------------------------------
__global__ __launch_bounds__(1024) void solve_kernel() {
    const int tid = threadIdx.x;
    const int b = blockIdx.x;
    const int i = tid >> 5;
    const int j = tid & 31;

    // chunk reduce: 32 partials -> 1
    {
        float2 g = make_float2(0.f, 0.f);
#pragma unroll
        for (int c = 0; c < CHUNK; c++) {
            float2 t = d_partial[b * CHUNK + c][tid];
            g.x += t.x; g.y += t.y;
        }
        d_chunk[b][tid] = g;
    }
    __threadfence();
    __syncthreads();
    __shared__ int sLast;
    if (tid == 0) sLast = (atomicAdd(&d_ticket, 1) == NCTA_B - 1) ? 1 : 0;
    __syncthreads();
    if (!sLast) return;
    if (tid == 0) d_ticket = 0;   // reset for next replay (deterministic)
    __threadfence();

    __shared__ float2 sG0[R][R + 1];
    __shared__ float2 sL[R][R + 1];
    __shared__ float2 sW[R][R + 1];
    __shared__ float2 sP[R][R + 1];
    __shared__ float2 sT[R][R + 1];
    __shared__ float  sScale[R];

    // final reduce 16 chunks -> G0
    {
        float2 g = make_float2(0.f, 0.f);
#pragma unroll
        for (int c = 0; c < NCTA_B; c++) {
            float2 t = d_chunk[c][tid];
            g.x += t.x; g.y += t.y;
        }
        sG0[i][j] = g;
        sL[i][j]  = g;
    }
    __syncthreads();

    // Cholesky (lower) in-place on sL: G0 = L L^H
    for (int k = 0; k < R; k++) {
        float inv = rsqrtf(sL[k][k].x);
        __syncthreads();
        if (j == k && i >= k) { sL[i][k].x *= inv; sL[i][k].y *= inv; }
        __syncthreads();
        if (i > k && j > k && j <= i) {
            float2 a = sL[i][k], bb = sL[j][k];
            sL[i][j].x -= a.x * bb.x + a.y * bb.y;   // -= a*conj(b)
            sL[i][j].y -= a.y * bb.x - a.x * bb.y;
        }
        __syncthreads();
    }

    // W = L^{-1} (lower): warp c -> column c by forward substitution; lane j holds w[j].
    {
        const int c = i;
        float wr = 0.f, wi = 0.f;
        if (j == c) wr = 1.0f / sL[c][c].x;
        for (int r = c + 1; r < R; r++) {
            float2 Lr = sL[r][j];
            float pr = 0.f, pi = 0.f;
            if (j >= c && j < r) {
                pr = Lr.x * wr - Lr.y * wi;
                pi = Lr.x * wi + Lr.y * wr;
            }
#pragma unroll
            for (int o = 16; o > 0; o >>= 1) {
                pr += __shfl_xor_sync(0xffffffffu, pr, o);
                pi += __shfl_xor_sync(0xffffffffu, pi, o);
            }
            float rinv = 1.0f / sL[r][r].x;
            if (j == r) { wr = -pr * rinv; wi = -pi * rinv; }
        }
        sW[j][c] = make_float2(wr, wi);
    }
    __syncthreads();

    // P = G0 * W^H
    {
        float pr = 0.f, pi = 0.f;
#pragma unroll
        for (int k = 0; k < R; k++) {
            float2 a = sG0[i][k];
            float2 bb = sW[j][k];
            pr += a.x * bb.x + a.y * bb.y;
            pi += a.y * bb.x - a.x * bb.y;
        }
        sP[i][j] = make_float2(pr, pi);
    }
    __syncthreads();

    // G = W * P (= Q^H Q); T = I - 0.5 off(G); scale_j = rsqrt(G_jj + eps)
    {
        float gr = 0.f, gi = 0.f;
#pragma unroll
        for (int k = 0; k < R; k++) {
            float2 a = sW[i][k];
            float2 bb = sP[k][j];
            gr += a.x * bb.x - a.y * bb.y;
            gi += a.x * bb.y + a.y * bb.x;
        }
        if (i == j) {
            sScale[j] = rsqrtf(gr + 1e-10f);
            sT[i][j] = make_float2(1.f, 0.f);
        } else {
            sT[i][j] = make_float2(-0.5f * gr, -0.5f * gi);
        }
    }
    __syncthreads();

    // S = W^H * T * diag(scale)
    {
        float sr = 0.f, si = 0.f;
#pragma unroll
        for (int k = 0; k < R; k++) {
            float2 a = sW[k][i];
            float2 bb = sT[k][j];
            sr += a.x * bb.x + a.y * bb.y;
            si += a.x * bb.y - a.y * bb.x;
        }
        float sc = sScale[j];
        d_S[i * R + j] = make_float2(sr * sc, si * sc);
    }
}

// ---------------------------------------------------------------------------
// Kernel C: out = X * S. Warp per row group; lane j: y_j = sum_k x_k S[k][j].
// ---------------------------------------------------------------------------
__global__ __launch_bounds__(256) void apply_kernel(const float2* __restrict__ x,
                                                    float2* __restrict__ out) {
    const int lane = threadIdx.x & 31;
    const int warp = threadIdx.x >> 5;
    const int row0 = (blockIdx.x * WARPS_A + warp) * ROWS_PER_WARP;

    float2 s[R];
#pragma unroll
    for (int k = 0; k < R; k++) s[k] = d_S[k * R + lane];

    const float2* p = x + (size_t)row0 * R + lane;
    float2* q = out + (size_t)row0 * R + lane;

    float2 v[ROWS_PER_WARP];
#pragma unroll
    for (int m = 0; m < ROWS_PER_WARP; m++) v[m] = p[m * R];

#pragma unroll
    for (int m = 0; m < ROWS_PER_WARP; m++) {
        float yr = 0.f, yi = 0.f;
#pragma unroll
        for (int k = 0; k < R; k++) {
            float xr = __shfl_sync(0xffffffffu, v[m].x, k);
            float xi = __shfl_sync(0xffffffffu, v[m].y, k);
            yr += xr * s[k].x - xi * s[k].y;
            yi += xr * s[k].y + xi * s[k].x;
        }
        q[m * R] = make_float2(yr, yi);
    }
}

extern "C" void kernel_launch(void* const* d_in, const int* in_sizes, int n_in,
                              void* d_out, int out_size) {
    const float2* x = (const float2*)d_in[0];
    float2* out = (float2*)d_out;
    gram_kernel<<<NCTA_A, 256>>>(x);
    solve_kernel<<<NCTA_B, 1024>>>();
    apply_kernel<<<NCTA_A, 256>>>(x, out);
}